// round 6
// baseline (speedup 1.0000x reference)
#include <cuda_runtime.h>
#include <cuda_bf16.h>

// Problem constants (fixed shapes for this problem)
#define NN 50000
#define EE 800000
#define DD 128
#define HH 32

// -------- scratch (no allocations allowed) --------
__device__ __align__(16) float g_y1[NN * HH];    // x @ W1_l^T
__device__ __align__(16) float g_z1[NN * HH];    // x @ W1_r^T
__device__ __align__(16) float g_agg[NN * HH];   // scatter-sum of y1
__device__ __align__(16) float g_deg[NN];
__device__ __align__(16) float g_sl[NN];         // h @ W2_l^T
__device__ __align__(16) float g_sr[NN];         // h @ W2_r^T
__device__ __align__(16) float g_agg2[NN];       // scatter-sum of s_l
__device__ int   g_is64;                         // edge_index dtype flag

__device__ __forceinline__ long long edge_at(const void* ei, long long pos, int is64) {
    if (is64) return ((const long long*)ei)[pos];
    return (long long)((const int*)ei)[pos];
}

// -------- init: detect dtype (block 0) + zero accumulators (vectorized) --------
__global__ void init_kernel(const unsigned* __restrict__ ei_words, int n) {
    if (blockIdx.x == 0) {
        __shared__ int flag;
        if (threadIdx.x == 0) flag = 1;
        __syncthreads();
        unsigned w = ei_words[2 * threadIdx.x + 1];  // high words if int64
        if (w != 0u) flag = 0;
        __syncthreads();
        if (threadIdx.x == 0) g_is64 = flag;
    }
    float4 z4 = make_float4(0.f, 0.f, 0.f, 0.f);
    int n_agg4 = n * HH / 4;
    float4* agg4 = (float4*)g_agg;
    for (int i = blockIdx.x * blockDim.x + threadIdx.x; i < n_agg4;
         i += gridDim.x * blockDim.x)
        agg4[i] = z4;
    for (int i = blockIdx.x * blockDim.x + threadIdx.x; i < n;
         i += gridDim.x * blockDim.x) {
        g_deg[i] = 0.0f;
        g_agg2[i] = 0.0f;
    }
}

// -------- tf32 helpers --------
__device__ __forceinline__ unsigned f2tf32(float f) {
    unsigned u;
    asm("cvt.rna.tf32.f32 %0, %1;" : "=r"(u) : "f"(f));
    return u;
}
__device__ __forceinline__ void split_tf32(float f, unsigned& hi, unsigned& lo) {
    hi = f2tf32(f);
    float rem = f - __uint_as_float(hi);
    lo = f2tf32(rem);
}
__device__ __forceinline__ void mma_tf32(float* d, unsigned a0, unsigned a1,
                                         unsigned a2, unsigned a3,
                                         unsigned b0, unsigned b1) {
    asm volatile(
        "mma.sync.aligned.m16n8k8.row.col.f32.tf32.tf32.f32 "
        "{%0,%1,%2,%3}, {%4,%5,%6,%7}, {%8,%9}, {%0,%1,%2,%3};\n"
        : "+f"(d[0]), "+f"(d[1]), "+f"(d[2]), "+f"(d[3])
        : "r"(a0), "r"(a1), "r"(a2), "r"(a3), "r"(b0), "r"(b1));
}

// Dynamic smem layout: xs[64][132] then wt[128][72]
#define XS_STRIDE 132
#define WT_STRIDE 72
#define XS_ELEMS  (64 * XS_STRIDE)
#define WT_ELEMS  (128 * WT_STRIDE)
#define LIN1_SMEM_BYTES ((XS_ELEMS + WT_ELEMS) * (int)sizeof(float))

// -------- fused linear via 3xTF32 tensor cores --------
__global__ __launch_bounds__(128) void lin1_mma_kernel(
    const float* __restrict__ x,
    const float* __restrict__ W1l,
    const float* __restrict__ W1r,
    int n)
{
    extern __shared__ float smem[];
    float (*xs)[XS_STRIDE] = (float (*)[XS_STRIDE])smem;              // 64 x 132
    float (*wt)[WT_STRIDE] = (float (*)[WT_STRIDE])(smem + XS_ELEMS); // 128 x 72

    int tid = threadIdx.x;
    int node0 = blockIdx.x * 64;

    for (int idx = tid; idx < DD * 64; idx += 128) {
        int k = idx & 127, j = idx >> 7;
        wt[k][j] = (j < HH) ? W1l[j * DD + k] : W1r[(j - HH) * DD + k];
    }
    for (int idx = tid; idx < 64 * (DD / 4); idx += 128) {
        int r = idx >> 5, c4 = idx & 31;
        float4 v = (node0 + r < n)
                 ? ((const float4*)(x + (size_t)(node0 + r) * DD))[c4]
                 : make_float4(0.f, 0.f, 0.f, 0.f);
        *(float4*)&xs[r][c4 * 4] = v;
    }
    __syncthreads();

    int warp = tid >> 5, lane = tid & 31;
    int g = lane >> 2, tig = lane & 3;
    int m0 = warp * 16;

    float acc[8][4];
#pragma unroll
    for (int nt = 0; nt < 8; nt++)
#pragma unroll
        for (int c = 0; c < 4; c++) acc[nt][c] = 0.0f;

#pragma unroll
    for (int kc = 0; kc < 16; kc++) {
        int k0 = kc * 8;
        float a0 = xs[m0 + g][k0 + tig];
        float a1 = xs[m0 + g + 8][k0 + tig];
        float a2 = xs[m0 + g][k0 + tig + 4];
        float a3 = xs[m0 + g + 8][k0 + tig + 4];
        unsigned ah0, al0, ah1, al1, ah2, al2, ah3, al3;
        split_tf32(a0, ah0, al0); split_tf32(a1, ah1, al1);
        split_tf32(a2, ah2, al2); split_tf32(a3, ah3, al3);

#pragma unroll
        for (int nt = 0; nt < 8; nt++) {
            float b0f = wt[k0 + tig][nt * 8 + g];
            float b1f = wt[k0 + tig + 4][nt * 8 + g];
            unsigned bh0, bl0, bh1, bl1;
            split_tf32(b0f, bh0, bl0); split_tf32(b1f, bh1, bl1);
            mma_tf32(acc[nt], ah0, ah1, ah2, ah3, bh0, bh1);  // hi*hi
            mma_tf32(acc[nt], al0, al1, al2, al3, bh0, bh1);  // lo*hi
            mma_tf32(acc[nt], ah0, ah1, ah2, ah3, bl0, bl1);  // hi*lo
        }
    }

    int node_a = node0 + m0 + g;
    int node_b = node_a + 8;
#pragma unroll
    for (int nt = 0; nt < 8; nt++) {
        int j = nt * 8 + 2 * tig;
        float* base = (j < HH) ? g_y1 : g_z1;
        int jj = j & 31;
        if (node_a < n) *(float2*)&base[node_a * HH + jj] = make_float2(acc[nt][0], acc[nt][1]);
        if (node_b < n) *(float2*)&base[node_b * HH + jj] = make_float2(acc[nt][2], acc[nt][3]);
    }
}

// -------- layer-1 edge scatter: 1 thread/edge, 8 unrolled float4 REDs --------
__global__ __launch_bounds__(256) void scatter1_kernel(const void* __restrict__ ei, long long E) {
    long long e = (long long)blockIdx.x * blockDim.x + threadIdx.x;
    if (e >= E) return;
    int is64 = g_is64;
    long long src = edge_at(ei, e, is64);
    long long dst = edge_at(ei, E + e, is64);
    const float4* row = (const float4*)&g_y1[src * HH];
    float4* drow = (float4*)&g_agg[dst * HH];
    float4 v0 = row[0], v1 = row[1], v2 = row[2], v3 = row[3];
    float4 v4 = row[4], v5 = row[5], v6 = row[6], v7 = row[7];
    atomicAdd(&drow[0], v0);
    atomicAdd(&drow[1], v1);
    atomicAdd(&drow[2], v2);
    atomicAdd(&drow[3], v3);
    atomicAdd(&drow[4], v4);
    atomicAdd(&drow[5], v5);
    atomicAdd(&drow[6], v6);
    atomicAdd(&drow[7], v7);
    atomicAdd(&g_deg[dst], 1.0f);
}

// -------- layer-1 epilogue + layer-2 linear: 4 threads/node --------
__global__ __launch_bounds__(256) void epi_kernel(
    const float* __restrict__ b1,
    const float* __restrict__ W2l,
    const float* __restrict__ W2r,
    int n)
{
    __shared__ float sb1[HH], swl[HH], swr[HH];
    if (threadIdx.x < HH) {
        sb1[threadIdx.x] = b1[threadIdx.x];
        swl[threadIdx.x] = W2l[threadIdx.x];
        swr[threadIdx.x] = W2r[threadIdx.x];
    }
    __syncthreads();
    int t = blockIdx.x * blockDim.x + threadIdx.x;
    int node = t >> 2;         // 4 threads per node
    int q = t & 3;             // this thread's 8-feature slice
    if (node >= n) return;

    const float4* ar = (const float4*)&g_agg[(size_t)node * HH + q * 8];
    const float4* zr = (const float4*)&g_z1[(size_t)node * HH + q * 8];
    float rdeg = 1.0f / fmaxf(g_deg[node], 1.0f);
    float sl = 0.0f, sr = 0.0f;
#pragma unroll
    for (int c = 0; c < 2; c++) {
        float4 a = ar[c];
        float4 z = zr[c];
        int k = q * 8 + c * 4;
        float h0 = fmaxf(fmaf(a.x, rdeg, sb1[k + 0] + z.x), 0.0f);
        float h1 = fmaxf(fmaf(a.y, rdeg, sb1[k + 1] + z.y), 0.0f);
        float h2 = fmaxf(fmaf(a.z, rdeg, sb1[k + 2] + z.z), 0.0f);
        float h3 = fmaxf(fmaf(a.w, rdeg, sb1[k + 3] + z.w), 0.0f);
        sl = fmaf(h0, swl[k + 0], sl); sr = fmaf(h0, swr[k + 0], sr);
        sl = fmaf(h1, swl[k + 1], sl); sr = fmaf(h1, swr[k + 1], sr);
        sl = fmaf(h2, swl[k + 2], sl); sr = fmaf(h2, swr[k + 2], sr);
        sl = fmaf(h3, swl[k + 3], sl); sr = fmaf(h3, swr[k + 3], sr);
    }
    // reduce across the 4 lanes handling this node (adjacent lanes)
    sl += __shfl_xor_sync(0xFFFFFFFFu, sl, 1);
    sr += __shfl_xor_sync(0xFFFFFFFFu, sr, 1);
    sl += __shfl_xor_sync(0xFFFFFFFFu, sl, 2);
    sr += __shfl_xor_sync(0xFFFFFFFFu, sr, 2);
    if (q == 0) { g_sl[node] = sl; g_sr[node] = sr; }
}

// -------- layer-2 edge scatter: agg2[dst] += s_l[src], 2 edges/thread --------
__global__ __launch_bounds__(256) void scatter2_kernel(const void* __restrict__ ei, long long E) {
    long long t = (long long)blockIdx.x * blockDim.x + threadIdx.x;
    long long half = (E + 1) >> 1;
    if (t >= half) return;
    int is64 = g_is64;
    long long e0 = t;
    long long e1 = t + half;
    long long s0 = edge_at(ei, e0, is64);
    long long d0 = edge_at(ei, E + e0, is64);
    float v0 = g_sl[s0];
    if (e1 < E) {
        long long s1 = edge_at(ei, e1, is64);
        long long d1 = edge_at(ei, E + e1, is64);
        float v1 = g_sl[s1];
        atomicAdd(&g_agg2[d0], v0);
        atomicAdd(&g_agg2[d1], v1);
    } else {
        atomicAdd(&g_agg2[d0], v0);
    }
}

// -------- final: sigmoid(agg2/deg + b2 + s_r) --------
__global__ __launch_bounds__(256) void final_kernel(const float* __restrict__ b2,
                                                    float* __restrict__ out, int n) {
    int i = blockIdx.x * blockDim.x + threadIdx.x;
    if (i >= n) return;
    float rdeg = 1.0f / fmaxf(g_deg[i], 1.0f);
    float v = fmaf(g_agg2[i], rdeg, b2[0] + g_sr[i]);
    out[i] = 1.0f / (1.0f + expf(-v));
}

extern "C" void kernel_launch(void* const* d_in, const int* in_sizes, int n_in,
                              void* d_out, int out_size) {
    const float* x   = (const float*)d_in[0];
    const void*  ei  = d_in[1];
    const float* W1l = (const float*)d_in[2];
    const float* b1  = (const float*)d_in[3];
    const float* W1r = (const float*)d_in[4];
    const float* W2l = (const float*)d_in[5];
    const float* b2  = (const float*)d_in[6];
    const float* W2r = (const float*)d_in[7];
    float* out = (float*)d_out;

    int n = in_sizes[0] / DD;            // 50000
    long long E = in_sizes[1] / 2;       // 800000

    cudaFuncSetAttribute(lin1_mma_kernel,
                         cudaFuncAttributeMaxDynamicSharedMemorySize,
                         LIN1_SMEM_BYTES);

    init_kernel<<<512, 256>>>((const unsigned*)ei, n);
    lin1_mma_kernel<<<(n + 63) / 64, 128, LIN1_SMEM_BYTES>>>(x, W1l, W1r, n);
    scatter1_kernel<<<(unsigned)((E + 255) / 256), 256>>>(ei, E);
    epi_kernel<<<(n * 4 + 255) / 256, 256>>>(b1, W2l, W2r, n);
    {
        long long half = (E + 1) >> 1;
        scatter2_kernel<<<(unsigned)((half + 255) / 256), 256>>>(ei, E);
    }
    final_kernel<<<(n + 255) / 256, 256>>>(b2, out, n);
}

// round 7
// speedup vs baseline: 1.3824x; 1.3824x over previous
#include <cuda_runtime.h>
#include <cuda_bf16.h>

// Problem constants (fixed shapes for this problem)
#define NN 50000
#define EE 800000
#define DD 128
#define HH 32

// -------- scratch (no allocations allowed) --------
__device__ __align__(16) float g_y1[NN * HH];    // x @ W1_l^T
__device__ __align__(16) float g_z1[NN * HH];    // x @ W1_r^T
__device__ __align__(16) float g_agg[NN * HH];   // scatter-sum of y1
__device__ __align__(16) float g_deg[NN];
__device__ __align__(16) float g_sl[NN];         // h @ W2_l^T
__device__ __align__(16) float g_sr[NN];         // h @ W2_r^T
__device__ __align__(16) float g_agg2[NN];       // scatter-sum of s_l
__device__ int   g_is64;                         // edge_index dtype flag

__device__ __forceinline__ long long edge_at(const void* ei, long long pos, int is64) {
    if (is64) return ((const long long*)ei)[pos];
    return (long long)((const int*)ei)[pos];
}

// -------- init: detect dtype (block 0) + zero accumulators (vectorized) --------
__global__ void init_kernel(const unsigned* __restrict__ ei_words, int n) {
    if (blockIdx.x == 0) {
        __shared__ int flag;
        if (threadIdx.x == 0) flag = 1;
        __syncthreads();
        unsigned w = ei_words[2 * threadIdx.x + 1];  // high words if int64
        if (w != 0u) flag = 0;
        __syncthreads();
        if (threadIdx.x == 0) g_is64 = flag;
    }
    float4 z4 = make_float4(0.f, 0.f, 0.f, 0.f);
    int n_agg4 = n * HH / 4;
    float4* agg4 = (float4*)g_agg;
    for (int i = blockIdx.x * blockDim.x + threadIdx.x; i < n_agg4;
         i += gridDim.x * blockDim.x)
        agg4[i] = z4;
    for (int i = blockIdx.x * blockDim.x + threadIdx.x; i < n;
         i += gridDim.x * blockDim.x) {
        g_deg[i] = 0.0f;
        g_agg2[i] = 0.0f;
    }
}

// -------- tf32 helpers --------
__device__ __forceinline__ unsigned f2tf32(float f) {
    unsigned u;
    asm("cvt.rna.tf32.f32 %0, %1;" : "=r"(u) : "f"(f));
    return u;
}
__device__ __forceinline__ void split_tf32(float f, unsigned& hi, unsigned& lo) {
    hi = f2tf32(f);
    float rem = f - __uint_as_float(hi);
    lo = f2tf32(rem);
}
__device__ __forceinline__ void mma_tf32(float* d, unsigned a0, unsigned a1,
                                         unsigned a2, unsigned a3,
                                         unsigned b0, unsigned b1) {
    asm volatile(
        "mma.sync.aligned.m16n8k8.row.col.f32.tf32.tf32.f32 "
        "{%0,%1,%2,%3}, {%4,%5,%6,%7}, {%8,%9}, {%0,%1,%2,%3};\n"
        : "+f"(d[0]), "+f"(d[1]), "+f"(d[2]), "+f"(d[3])
        : "r"(a0), "r"(a1), "r"(a2), "r"(a3), "r"(b0), "r"(b1));
}

// Dynamic smem layout: xs[64][132] then wt[128][72]
#define XS_STRIDE 132
#define WT_STRIDE 72
#define XS_ELEMS  (64 * XS_STRIDE)
#define WT_ELEMS  (128 * WT_STRIDE)
#define LIN1_SMEM_BYTES ((XS_ELEMS + WT_ELEMS) * (int)sizeof(float))

// -------- fused linear via 3xTF32 tensor cores --------
__global__ __launch_bounds__(128) void lin1_mma_kernel(
    const float* __restrict__ x,
    const float* __restrict__ W1l,
    const float* __restrict__ W1r,
    int n)
{
    extern __shared__ float smem[];
    float (*xs)[XS_STRIDE] = (float (*)[XS_STRIDE])smem;              // 64 x 132
    float (*wt)[WT_STRIDE] = (float (*)[WT_STRIDE])(smem + XS_ELEMS); // 128 x 72

    int tid = threadIdx.x;
    int node0 = blockIdx.x * 64;

    for (int idx = tid; idx < DD * 64; idx += 128) {
        int k = idx & 127, j = idx >> 7;
        wt[k][j] = (j < HH) ? W1l[j * DD + k] : W1r[(j - HH) * DD + k];
    }
    for (int idx = tid; idx < 64 * (DD / 4); idx += 128) {
        int r = idx >> 5, c4 = idx & 31;
        float4 v = (node0 + r < n)
                 ? ((const float4*)(x + (size_t)(node0 + r) * DD))[c4]
                 : make_float4(0.f, 0.f, 0.f, 0.f);
        *(float4*)&xs[r][c4 * 4] = v;
    }
    __syncthreads();

    int warp = tid >> 5, lane = tid & 31;
    int g = lane >> 2, tig = lane & 3;
    int m0 = warp * 16;

    float acc[8][4];
#pragma unroll
    for (int nt = 0; nt < 8; nt++)
#pragma unroll
        for (int c = 0; c < 4; c++) acc[nt][c] = 0.0f;

#pragma unroll
    for (int kc = 0; kc < 16; kc++) {
        int k0 = kc * 8;
        float a0 = xs[m0 + g][k0 + tig];
        float a1 = xs[m0 + g + 8][k0 + tig];
        float a2 = xs[m0 + g][k0 + tig + 4];
        float a3 = xs[m0 + g + 8][k0 + tig + 4];
        unsigned ah0, al0, ah1, al1, ah2, al2, ah3, al3;
        split_tf32(a0, ah0, al0); split_tf32(a1, ah1, al1);
        split_tf32(a2, ah2, al2); split_tf32(a3, ah3, al3);

#pragma unroll
        for (int nt = 0; nt < 8; nt++) {
            float b0f = wt[k0 + tig][nt * 8 + g];
            float b1f = wt[k0 + tig + 4][nt * 8 + g];
            unsigned bh0, bl0, bh1, bl1;
            split_tf32(b0f, bh0, bl0); split_tf32(b1f, bh1, bl1);
            mma_tf32(acc[nt], ah0, ah1, ah2, ah3, bh0, bh1);  // hi*hi
            mma_tf32(acc[nt], al0, al1, al2, al3, bh0, bh1);  // lo*hi
            mma_tf32(acc[nt], ah0, ah1, ah2, ah3, bl0, bl1);  // hi*lo
        }
    }

    int node_a = node0 + m0 + g;
    int node_b = node_a + 8;
#pragma unroll
    for (int nt = 0; nt < 8; nt++) {
        int j = nt * 8 + 2 * tig;
        float* base = (j < HH) ? g_y1 : g_z1;
        int jj = j & 31;
        if (node_a < n) *(float2*)&base[node_a * HH + jj] = make_float2(acc[nt][0], acc[nt][1]);
        if (node_b < n) *(float2*)&base[node_b * HH + jj] = make_float2(acc[nt][2], acc[nt][3]);
    }
}

// -------- layer-1 edge scatter: agg[dst] += y1[src], deg[dst] += 1 --------
// 8 threads per edge, float4 vector atomics: each RED wavefront covers only
// 4 dst rows in contiguous 128B runs (compact lane addresses -> few L2 txns).
__global__ __launch_bounds__(256) void scatter1_kernel(const void* __restrict__ ei, long long E) {
    long long t = (long long)blockIdx.x * blockDim.x + threadIdx.x;
    long long e = t >> 3;
    int sub = (int)(t & 7);
    if (e >= E) return;
    int is64 = g_is64;
    long long src = edge_at(ei, e, is64);
    long long dst = edge_at(ei, E + e, is64);
    float4 v = *(const float4*)&g_y1[src * HH + sub * 4];
    atomicAdd((float4*)&g_agg[dst * HH + sub * 4], v);
    if (sub == 0) atomicAdd(&g_deg[dst], 1.0f);
}

// -------- layer-1 epilogue + layer-2 linear: 4 threads/node --------
__global__ __launch_bounds__(256) void epi_kernel(
    const float* __restrict__ b1,
    const float* __restrict__ W2l,
    const float* __restrict__ W2r,
    int n)
{
    __shared__ float sb1[HH], swl[HH], swr[HH];
    if (threadIdx.x < HH) {
        sb1[threadIdx.x] = b1[threadIdx.x];
        swl[threadIdx.x] = W2l[threadIdx.x];
        swr[threadIdx.x] = W2r[threadIdx.x];
    }
    __syncthreads();
    int t = blockIdx.x * blockDim.x + threadIdx.x;
    int node = t >> 2;         // 4 threads per node
    int q = t & 3;             // this thread's 8-feature slice
    if (node >= n) return;

    const float4* ar = (const float4*)&g_agg[(size_t)node * HH + q * 8];
    const float4* zr = (const float4*)&g_z1[(size_t)node * HH + q * 8];
    float rdeg = 1.0f / fmaxf(g_deg[node], 1.0f);
    float sl = 0.0f, sr = 0.0f;
#pragma unroll
    for (int c = 0; c < 2; c++) {
        float4 a = ar[c];
        float4 z = zr[c];
        int k = q * 8 + c * 4;
        float h0 = fmaxf(fmaf(a.x, rdeg, sb1[k + 0] + z.x), 0.0f);
        float h1 = fmaxf(fmaf(a.y, rdeg, sb1[k + 1] + z.y), 0.0f);
        float h2 = fmaxf(fmaf(a.z, rdeg, sb1[k + 2] + z.z), 0.0f);
        float h3 = fmaxf(fmaf(a.w, rdeg, sb1[k + 3] + z.w), 0.0f);
        sl = fmaf(h0, swl[k + 0], sl); sr = fmaf(h0, swr[k + 0], sr);
        sl = fmaf(h1, swl[k + 1], sl); sr = fmaf(h1, swr[k + 1], sr);
        sl = fmaf(h2, swl[k + 2], sl); sr = fmaf(h2, swr[k + 2], sr);
        sl = fmaf(h3, swl[k + 3], sl); sr = fmaf(h3, swr[k + 3], sr);
    }
    // reduce across the 4 lanes handling this node (adjacent lanes)
    sl += __shfl_xor_sync(0xFFFFFFFFu, sl, 1);
    sr += __shfl_xor_sync(0xFFFFFFFFu, sr, 1);
    sl += __shfl_xor_sync(0xFFFFFFFFu, sl, 2);
    sr += __shfl_xor_sync(0xFFFFFFFFu, sr, 2);
    if (q == 0) { g_sl[node] = sl; g_sr[node] = sr; }
}

// -------- layer-2 edge scatter: agg2[dst] += s_l[src], 2 edges/thread --------
__global__ __launch_bounds__(256) void scatter2_kernel(const void* __restrict__ ei, long long E) {
    long long t = (long long)blockIdx.x * blockDim.x + threadIdx.x;
    long long half = (E + 1) >> 1;
    if (t >= half) return;
    int is64 = g_is64;
    long long e0 = t;
    long long e1 = t + half;
    long long s0 = edge_at(ei, e0, is64);
    long long d0 = edge_at(ei, E + e0, is64);
    float v0 = g_sl[s0];
    if (e1 < E) {
        long long s1 = edge_at(ei, e1, is64);
        long long d1 = edge_at(ei, E + e1, is64);
        float v1 = g_sl[s1];
        atomicAdd(&g_agg2[d0], v0);
        atomicAdd(&g_agg2[d1], v1);
    } else {
        atomicAdd(&g_agg2[d0], v0);
    }
}

// -------- final: sigmoid(agg2/deg + b2 + s_r) --------
__global__ __launch_bounds__(256) void final_kernel(const float* __restrict__ b2,
                                                    float* __restrict__ out, int n) {
    int i = blockIdx.x * blockDim.x + threadIdx.x;
    if (i >= n) return;
    float rdeg = 1.0f / fmaxf(g_deg[i], 1.0f);
    float v = fmaf(g_agg2[i], rdeg, b2[0] + g_sr[i]);
    out[i] = 1.0f / (1.0f + expf(-v));
}

extern "C" void kernel_launch(void* const* d_in, const int* in_sizes, int n_in,
                              void* d_out, int out_size) {
    const float* x   = (const float*)d_in[0];
    const void*  ei  = d_in[1];
    const float* W1l = (const float*)d_in[2];
    const float* b1  = (const float*)d_in[3];
    const float* W1r = (const float*)d_in[4];
    const float* W2l = (const float*)d_in[5];
    const float* b2  = (const float*)d_in[6];
    const float* W2r = (const float*)d_in[7];
    float* out = (float*)d_out;

    int n = in_sizes[0] / DD;            // 50000
    long long E = in_sizes[1] / 2;       // 800000

    cudaFuncSetAttribute(lin1_mma_kernel,
                         cudaFuncAttributeMaxDynamicSharedMemorySize,
                         LIN1_SMEM_BYTES);

    init_kernel<<<512, 256>>>((const unsigned*)ei, n);
    lin1_mma_kernel<<<(n + 63) / 64, 128, LIN1_SMEM_BYTES>>>(x, W1l, W1r, n);
    {
        long long threads = E * 8;
        scatter1_kernel<<<(unsigned)((threads + 255) / 256), 256>>>(ei, E);
    }
    epi_kernel<<<(n * 4 + 255) / 256, 256>>>(b1, W2l, W2r, n);
    {
        long long half = (E + 1) >> 1;
        scatter2_kernel<<<(unsigned)((half + 255) / 256), 256>>>(ei, E);
    }
    final_kernel<<<(n + 255) / 256, 256>>>(b2, out, n);
}

// round 8
// speedup vs baseline: 1.3885x; 1.0044x over previous
#include <cuda_runtime.h>
#include <cuda_bf16.h>

// Problem constants (fixed shapes for this problem)
#define NN 50000
#define EE 800000
#define DD 128
#define HH 32

// -------- scratch (no allocations allowed) --------
__device__ __align__(16) float g_y1[NN * HH];    // x @ W1_l^T
__device__ __align__(16) float g_z1[NN * HH];    // x @ W1_r^T
__device__ __align__(16) float g_agg[NN * HH];   // scatter-sum of y1
__device__ __align__(16) float g_deg[NN];
__device__ __align__(16) float g_sl[NN];         // h @ W2_l^T
__device__ __align__(16) float g_sr[NN];         // h @ W2_r^T
__device__ __align__(16) float g_agg2[NN];       // scatter-sum of s_l
__device__ int   g_is64;                         // edge_index dtype flag

// load node index (always < 2^31) as 32-bit regardless of storage width
__device__ __forceinline__ int edge_at32(const void* ei, long long pos, int is64) {
    // little-endian: low word of int64 is at [2*pos]
    return is64 ? ((const int*)ei)[2 * pos] : ((const int*)ei)[pos];
}

// -------- init: detect dtype (block 0) + zero accumulators (vectorized) --------
__global__ void init_kernel(const unsigned* __restrict__ ei_words, int n) {
    if (blockIdx.x == 0) {
        __shared__ int flag;
        if (threadIdx.x == 0) flag = 1;
        __syncthreads();
        unsigned w = ei_words[2 * threadIdx.x + 1];  // high words if int64
        if (w != 0u) flag = 0;
        __syncthreads();
        if (threadIdx.x == 0) g_is64 = flag;
    }
    float4 z4 = make_float4(0.f, 0.f, 0.f, 0.f);
    int n_agg4 = n * HH / 4;
    float4* agg4 = (float4*)g_agg;
    for (int i = blockIdx.x * blockDim.x + threadIdx.x; i < n_agg4;
         i += gridDim.x * blockDim.x)
        agg4[i] = z4;
    for (int i = blockIdx.x * blockDim.x + threadIdx.x; i < n;
         i += gridDim.x * blockDim.x) {
        g_deg[i] = 0.0f;
        g_agg2[i] = 0.0f;
    }
}

// -------- tf32 helpers --------
__device__ __forceinline__ unsigned f2tf32(float f) {
    unsigned u;
    asm("cvt.rna.tf32.f32 %0, %1;" : "=r"(u) : "f"(f));
    return u;
}
__device__ __forceinline__ void split_tf32(float f, unsigned& hi, unsigned& lo) {
    hi = f2tf32(f);
    float rem = f - __uint_as_float(hi);
    lo = f2tf32(rem);
}
__device__ __forceinline__ void mma_tf32(float* d, unsigned a0, unsigned a1,
                                         unsigned a2, unsigned a3,
                                         unsigned b0, unsigned b1) {
    asm volatile(
        "mma.sync.aligned.m16n8k8.row.col.f32.tf32.tf32.f32 "
        "{%0,%1,%2,%3}, {%4,%5,%6,%7}, {%8,%9}, {%0,%1,%2,%3};\n"
        : "+f"(d[0]), "+f"(d[1]), "+f"(d[2]), "+f"(d[3])
        : "r"(a0), "r"(a1), "r"(a2), "r"(a3), "r"(b0), "r"(b1));
}

// Dynamic smem layout: xs[64][132] then wt[128][72]
#define XS_STRIDE 132
#define WT_STRIDE 72
#define XS_ELEMS  (64 * XS_STRIDE)
#define WT_ELEMS  (128 * WT_STRIDE)
#define LIN1_SMEM_BYTES ((XS_ELEMS + WT_ELEMS) * (int)sizeof(float))

// -------- fused linear via 3xTF32 tensor cores --------
__global__ __launch_bounds__(128) void lin1_mma_kernel(
    const float* __restrict__ x,
    const float* __restrict__ W1l,
    const float* __restrict__ W1r,
    int n)
{
    extern __shared__ float smem[];
    float (*xs)[XS_STRIDE] = (float (*)[XS_STRIDE])smem;              // 64 x 132
    float (*wt)[WT_STRIDE] = (float (*)[WT_STRIDE])(smem + XS_ELEMS); // 128 x 72

    int tid = threadIdx.x;
    int node0 = blockIdx.x * 64;

    for (int idx = tid; idx < DD * 64; idx += 128) {
        int k = idx & 127, j = idx >> 7;
        wt[k][j] = (j < HH) ? W1l[j * DD + k] : W1r[(j - HH) * DD + k];
    }
    for (int idx = tid; idx < 64 * (DD / 4); idx += 128) {
        int r = idx >> 5, c4 = idx & 31;
        float4 v = (node0 + r < n)
                 ? ((const float4*)(x + (size_t)(node0 + r) * DD))[c4]
                 : make_float4(0.f, 0.f, 0.f, 0.f);
        *(float4*)&xs[r][c4 * 4] = v;
    }
    __syncthreads();

    int warp = tid >> 5, lane = tid & 31;
    int g = lane >> 2, tig = lane & 3;
    int m0 = warp * 16;

    float acc[8][4];
#pragma unroll
    for (int nt = 0; nt < 8; nt++)
#pragma unroll
        for (int c = 0; c < 4; c++) acc[nt][c] = 0.0f;

#pragma unroll
    for (int kc = 0; kc < 16; kc++) {
        int k0 = kc * 8;
        float a0 = xs[m0 + g][k0 + tig];
        float a1 = xs[m0 + g + 8][k0 + tig];
        float a2 = xs[m0 + g][k0 + tig + 4];
        float a3 = xs[m0 + g + 8][k0 + tig + 4];
        unsigned ah0, al0, ah1, al1, ah2, al2, ah3, al3;
        split_tf32(a0, ah0, al0); split_tf32(a1, ah1, al1);
        split_tf32(a2, ah2, al2); split_tf32(a3, ah3, al3);

#pragma unroll
        for (int nt = 0; nt < 8; nt++) {
            float b0f = wt[k0 + tig][nt * 8 + g];
            float b1f = wt[k0 + tig + 4][nt * 8 + g];
            unsigned bh0, bl0, bh1, bl1;
            split_tf32(b0f, bh0, bl0); split_tf32(b1f, bh1, bl1);
            mma_tf32(acc[nt], ah0, ah1, ah2, ah3, bh0, bh1);  // hi*hi
            mma_tf32(acc[nt], al0, al1, al2, al3, bh0, bh1);  // lo*hi
            mma_tf32(acc[nt], ah0, ah1, ah2, ah3, bl0, bl1);  // hi*lo
        }
    }

    int node_a = node0 + m0 + g;
    int node_b = node_a + 8;
#pragma unroll
    for (int nt = 0; nt < 8; nt++) {
        int j = nt * 8 + 2 * tig;
        float* base = (j < HH) ? g_y1 : g_z1;
        int jj = j & 31;
        if (node_a < n) *(float2*)&base[node_a * HH + jj] = make_float2(acc[nt][0], acc[nt][1]);
        if (node_b < n) *(float2*)&base[node_b * HH + jj] = make_float2(acc[nt][2], acc[nt][3]);
    }
}

// -------- layer-1 edge scatter: cooperative 8-edges-per-8-lane-group --------
// Each thread preloads ONE edge's (src,dst) as 32-bit; the 8-lane group then
// processes its 8 edges via shfl broadcast. Per-edge issued ops drop ~4x vs
// redundant-load formulation; RED wavefronts still cover only 4 dst rows each.
__global__ __launch_bounds__(256) void scatter1_kernel(const void* __restrict__ ei, long long E) {
    long long t = (long long)blockIdx.x * blockDim.x + threadIdx.x;
    long long base = (t >> 3) * 8;       // first edge of this group
    int sub = (int)(t & 7);              // this lane's feature chunk
    int is64 = g_is64;

    long long my_e = base + sub;
    int my_src = 0, my_dst = 0;
    bool my_valid = (my_e < E);
    if (my_valid) {
        my_src = edge_at32(ei, my_e, is64);
        my_dst = edge_at32(ei, E + my_e, is64);
    }
    int lane = threadIdx.x & 31;
    int gbase = lane & ~7;               // leader lane of this 8-group

#pragma unroll
    for (int i = 0; i < 8; i++) {
        int s = __shfl_sync(0xFFFFFFFFu, my_src, gbase + i);
        int d = __shfl_sync(0xFFFFFFFFu, my_dst, gbase + i);
        if (base + i < E) {
            float4 v = *(const float4*)&g_y1[s * HH + sub * 4];
            atomicAdd((float4*)&g_agg[d * HH + sub * 4], v);
        }
    }
    if (my_valid) atomicAdd(&g_deg[my_dst], 1.0f);
}

// -------- layer-1 epilogue + layer-2 linear: 8 threads/node --------
__global__ __launch_bounds__(256) void epi_kernel(
    const float* __restrict__ b1,
    const float* __restrict__ W2l,
    const float* __restrict__ W2r,
    int n)
{
    __shared__ float sb1[HH], swl[HH], swr[HH];
    if (threadIdx.x < HH) {
        sb1[threadIdx.x] = b1[threadIdx.x];
        swl[threadIdx.x] = W2l[threadIdx.x];
        swr[threadIdx.x] = W2r[threadIdx.x];
    }
    __syncthreads();
    int t = blockIdx.x * blockDim.x + threadIdx.x;
    int node = t >> 3;         // 8 threads per node
    int q = t & 7;             // 4-feature slice
    bool valid = (node < n);
    int nd = valid ? node : (n - 1);   // clamp (keep full warp for shfl)

    float4 a = *(const float4*)&g_agg[(size_t)nd * HH + q * 4];
    float4 z = *(const float4*)&g_z1[(size_t)nd * HH + q * 4];
    float rdeg = 1.0f / fmaxf(g_deg[nd], 1.0f);
    int k = q * 4;
    float h0 = fmaxf(fmaf(a.x, rdeg, sb1[k + 0] + z.x), 0.0f);
    float h1 = fmaxf(fmaf(a.y, rdeg, sb1[k + 1] + z.y), 0.0f);
    float h2 = fmaxf(fmaf(a.z, rdeg, sb1[k + 2] + z.z), 0.0f);
    float h3 = fmaxf(fmaf(a.w, rdeg, sb1[k + 3] + z.w), 0.0f);
    float sl = h0 * swl[k + 0] + h1 * swl[k + 1] + h2 * swl[k + 2] + h3 * swl[k + 3];
    float sr = h0 * swr[k + 0] + h1 * swr[k + 1] + h2 * swr[k + 2] + h3 * swr[k + 3];
    // reduce across the 8 lanes handling this node (adjacent lanes)
    sl += __shfl_xor_sync(0xFFFFFFFFu, sl, 1);
    sr += __shfl_xor_sync(0xFFFFFFFFu, sr, 1);
    sl += __shfl_xor_sync(0xFFFFFFFFu, sl, 2);
    sr += __shfl_xor_sync(0xFFFFFFFFu, sr, 2);
    sl += __shfl_xor_sync(0xFFFFFFFFu, sl, 4);
    sr += __shfl_xor_sync(0xFFFFFFFFu, sr, 4);
    if (valid && q == 0) { g_sl[node] = sl; g_sr[node] = sr; }
}

// -------- layer-2 edge scatter: agg2[dst] += s_l[src], 2 edges/thread --------
__global__ __launch_bounds__(256) void scatter2_kernel(const void* __restrict__ ei, long long E) {
    long long t = (long long)blockIdx.x * blockDim.x + threadIdx.x;
    long long half = (E + 1) >> 1;
    if (t >= half) return;
    int is64 = g_is64;
    long long e0 = t;
    long long e1 = t + half;
    int s0 = edge_at32(ei, e0, is64);
    int d0 = edge_at32(ei, E + e0, is64);
    float v0 = g_sl[s0];
    if (e1 < E) {
        int s1 = edge_at32(ei, e1, is64);
        int d1 = edge_at32(ei, E + e1, is64);
        float v1 = g_sl[s1];
        atomicAdd(&g_agg2[d0], v0);
        atomicAdd(&g_agg2[d1], v1);
    } else {
        atomicAdd(&g_agg2[d0], v0);
    }
}

// -------- final: sigmoid(agg2/deg + b2 + s_r) --------
__global__ __launch_bounds__(256) void final_kernel(const float* __restrict__ b2,
                                                    float* __restrict__ out, int n) {
    int i = blockIdx.x * blockDim.x + threadIdx.x;
    if (i >= n) return;
    float rdeg = 1.0f / fmaxf(g_deg[i], 1.0f);
    float v = fmaf(g_agg2[i], rdeg, b2[0] + g_sr[i]);
    out[i] = 1.0f / (1.0f + expf(-v));
}

extern "C" void kernel_launch(void* const* d_in, const int* in_sizes, int n_in,
                              void* d_out, int out_size) {
    const float* x   = (const float*)d_in[0];
    const void*  ei  = d_in[1];
    const float* W1l = (const float*)d_in[2];
    const float* b1  = (const float*)d_in[3];
    const float* W1r = (const float*)d_in[4];
    const float* W2l = (const float*)d_in[5];
    const float* b2  = (const float*)d_in[6];
    const float* W2r = (const float*)d_in[7];
    float* out = (float*)d_out;

    int n = in_sizes[0] / DD;            // 50000
    long long E = in_sizes[1] / 2;       // 800000

    cudaFuncSetAttribute(lin1_mma_kernel,
                         cudaFuncAttributeMaxDynamicSharedMemorySize,
                         LIN1_SMEM_BYTES);

    init_kernel<<<512, 256>>>((const unsigned*)ei, n);
    lin1_mma_kernel<<<(n + 63) / 64, 128, LIN1_SMEM_BYTES>>>(x, W1l, W1r, n);
    {
        long long threads = ((E + 7) >> 3) << 3;   // one thread per edge, groups of 8
        scatter1_kernel<<<(unsigned)((threads + 255) / 256), 256>>>(ei, E);
    }
    epi_kernel<<<(n * 8 + 255) / 256, 256>>>(b1, W2l, W2r, n);
    {
        long long half = (E + 1) >> 1;
        scatter2_kernel<<<(unsigned)((half + 255) / 256), 256>>>(ei, E);
    }
    final_kernel<<<(n + 255) / 256, 256>>>(b2, out, n);
}